// round 10
// baseline (speedup 1.0000x reference)
#include <cuda_runtime.h>
#include <math.h>

#define NPTS   2048
#define NB     16
#define NCHUNK 8          // n-dimension split per batch
#define MSPLIT 2          // m-dimension split (occupancy: 2 blocks/SM)
#define TPB    256
#define MB     4          // m-points per thread (TPB*MB*MSPLIT = NPTS)
#define NBLK   (NB * NCHUNK * MSPLIT)   // 256
#define NSUM   (NB * NCHUNK)            // 128 s-sum slots (ms==0 blocks only)

typedef unsigned long long ull;

// Zero-initialized at module load. Key encoding makes 0 the identity of
// atomicMax (== +inf under min-over-floats), so no init pass is needed;
// the last block re-arms entries back to 0 each replay.
__device__ unsigned g_min[NB * NPTS];   // per-(b,m) running min, order-REVERSED keys
__device__ float    g_ssum[NSUM];       // per-(b,nc) partial sums of |p|^2
__device__ unsigned g_count = 0;        // arrival counter for last-block-done

// ---- packed f32x2 helpers (sm_103a) ----
__device__ __forceinline__ ull pk2(float a, float b) {
    ull r; asm("mov.b64 %0, {%1, %2};" : "=l"(r) : "f"(a), "f"(b)); return r;
}
__device__ __forceinline__ ull fma2(ull a, ull b, ull c) {
    ull d; asm("fma.rn.f32x2 %0, %1, %2, %3;" : "=l"(d) : "l"(a), "l"(b), "l"(c)); return d;
}
__device__ __forceinline__ void upk2(ull v, float& a, float& b) {
    asm("mov.b64 {%0, %1}, %2;" : "=f"(a), "=f"(b) : "l"(v));
}

// ---- order-REVERSING float<->uint keys: min(float) == max(key), identity = 0 ----
__device__ __forceinline__ unsigned fencMax(float f) {
    unsigned u = __float_as_uint(f);
    return (u & 0x80000000u) ? u : (~u & 0x7FFFFFFFu);
}
__device__ __forceinline__ float fdecMax(unsigned k) {
    unsigned u = (k & 0x80000000u) ? k : (~k & 0x7FFFFFFFu);
    return __uint_as_float(u);
}

__device__ __forceinline__ void quat2mat(const float q[4], float R[3][3]) {
    float w = q[0], x = q[1], y = q[2], z = q[3];
    R[0][0] = 1.f - 2.f * (y * y + z * z);
    R[0][1] = 2.f * (x * y - w * z);
    R[0][2] = 2.f * (x * z + w * y);
    R[1][0] = 2.f * (x * y + w * z);
    R[1][1] = 1.f - 2.f * (x * x + z * z);
    R[1][2] = 2.f * (y * z - w * x);
    R[2][0] = 2.f * (x * z - w * y);
    R[2][1] = 2.f * (y * z + w * x);
    R[2][2] = 1.f - 2.f * (x * x + y * y);
}

// Single fused kernel. grid = 16 batches x 8 n-chunks x 2 m-halves, 256 threads.
__global__ __launch_bounds__(TPB) void fused_kernel(const float* __restrict__ pq,
                                                    const float* __restrict__ gq,
                                                    const float* __restrict__ points,
                                                    float* __restrict__ out) {
    // n-table, packed-pair layout (readable as ull2):
    //   smA[j] = { pair(r0[2j],r0[2j+1]), pair(r1[2j],r1[2j+1]) }
    //   smB[j] = { pair(r2[2j],r2[2j+1]), pair(s [2j],s [2j+1]) }
    __shared__ ull   smA[TPB];          // [j*2+0]=r0 pair, [j*2+1]=r1 pair
    __shared__ ull   smB[TPB];          // [j*2+0]=r2 pair, [j*2+1]=s  pair
    __shared__ float sA[9];
    __shared__ float red[TPB / 32];
    __shared__ bool  isLast;

    const int b   = blockIdx.x >> 4;                 // batch
    const int nc  = (blockIdx.x >> 1) & (NCHUNK - 1);// n-chunk
    const int ms  = blockIdx.x & (MSPLIT - 1);       // m-half
    const int tid = threadIdx.x;
    const float* __restrict__ P = points + b * 3 * NPTS;

    // ---- per-block quaternion math: A = Rp^T * Rg for this batch ----
    if (tid == 0) {
        float p[4], g[4];
#pragma unroll
        for (int i = 0; i < 4; i++) { p[i] = pq[b * 4 + i]; g[i] = gq[b * 4 + i]; }
        float np2 = 0.f, ng2 = 0.f;
#pragma unroll
        for (int i = 0; i < 4; i++) { np2 += p[i] * p[i]; ng2 += g[i] * g[i]; }
        float ip = 1.f / fmaxf(sqrtf(np2), 1e-8f);
        float ig = 1.f / fmaxf(sqrtf(ng2), 1e-8f);
#pragma unroll
        for (int i = 0; i < 4; i++) { p[i] *= ip; g[i] *= ig; }
        float Rp[3][3], Rg[3][3];
        quat2mat(p, Rp);
        quat2mat(g, Rg);
#pragma unroll
        for (int i = 0; i < 3; i++)
#pragma unroll
            for (int j = 0; j < 3; j++) {
                float a = 0.f;
#pragma unroll
                for (int k = 0; k < 3; k++) a += Rp[k][i] * Rg[k][j];
                sA[i * 3 + j] = a;
            }
    }

    // ---- cos_loss: block 0, warp 0 (lanes 0..15 own one batch each) ----
    if (blockIdx.x == 0 && tid < 32) {
        float cos_term = 0.f;
        if (tid < NB) {
            float p[4], g[4];
#pragma unroll
            for (int i = 0; i < 4; i++) { p[i] = pq[tid * 4 + i]; g[i] = gq[tid * 4 + i]; }
            float dot = 0.f, np2 = 0.f, ng2 = 0.f;
#pragma unroll
            for (int i = 0; i < 4; i++) {
                dot += p[i] * g[i]; np2 += p[i] * p[i]; ng2 += g[i] * g[i];
            }
            cos_term = 1.f - dot / fmaxf(sqrtf(np2) * sqrtf(ng2), 1e-8f);
        }
#pragma unroll
        for (int o = 16; o > 0; o >>= 1) cos_term += __shfl_down_sync(0xFFFFFFFFu, cos_term, o);
        if (tid == 0) out[0] = cos_term * (1.f / (float)NB);
    }
    __syncthreads();

    const float A00 = sA[0], A01 = sA[1], A02 = sA[2];
    const float A10 = sA[3], A11 = sA[4], A12 = sA[5];
    const float A20 = sA[6], A21 = sA[7], A22 = sA[8];

    // ---- Phase 1: r/s table for this block's 256 n-points (+ s-sum, ms==0 only) ----
    {
        int n = nc * TPB + tid;
        float x = P[n], y = P[NPTS + n], z = P[2 * NPTS + n];
        float r0 = A00 * x + A01 * y + A02 * z;
        float r1 = A10 * x + A11 * y + A12 * z;
        float r2 = A20 * x + A21 * y + A22 * z;
        float s  = x * x + y * y + z * z;
        float* fA = (float*)smA;
        float* fB = (float*)smB;
        int j = tid >> 1, h = tid & 1;
        fA[j * 4 + h]     = r0;
        fA[j * 4 + 2 + h] = r1;
        fB[j * 4 + h]     = r2;
        fB[j * 4 + 2 + h] = s;

        if (ms == 0) {
            float t = s;
#pragma unroll
            for (int o = 16; o > 0; o >>= 1) t += __shfl_down_sync(0xFFFFFFFFu, t, o);
            if ((tid & 31) == 0) red[tid >> 5] = t;
        }
    }
    __syncthreads();
    if (ms == 0 && tid < (TPB / 32)) {
        float t = red[tid];
#pragma unroll
        for (int o = (TPB / 64); o > 0; o >>= 1) t += __shfl_down_sync(0xFFu, t, o);
        if (tid == 0) g_ssum[b * NCHUNK + nc] = t;
    }

    // ---- Phase 2: each thread owns m = ms*1024 + k*256 + tid, k in [0,4) ----
    const int mbase = ms * (NPTS / MSPLIT);
    ull u0[MB], u1[MB], u2[MB];
#pragma unroll
    for (int k = 0; k < MB; k++) {
        int m = mbase + k * TPB + tid;
        float mx = -2.f * P[m];
        float my = -2.f * P[NPTS + m];
        float mz = -2.f * P[2 * NPTS + m];
        u0[k] = pk2(mx, mx);
        u1[k] = pk2(my, my);
        u2[k] = pk2(mz, mz);
    }

    float mna[MB], mnb[MB];
#pragma unroll
    for (int k = 0; k < MB; k++) { mna[k] = INFINITY; mnb[k] = INFINITY; }

    const ull* __restrict__ pA = smA;
    const ull* __restrict__ pB = smB;
#pragma unroll 4
    for (int j = 0; j < TPB / 2; j++) {
        // LDS.128 -> two 64-bit packed operands each, no pack MOVs
        ull rp0 = pA[j * 2 + 0];
        ull rp1 = pA[j * 2 + 1];
        ull rp2 = pB[j * 2 + 0];
        ull sp  = pB[j * 2 + 1];
#pragma unroll
        for (int k = 0; k < MB; k++) {
            ull t = fma2(rp2, u2[k], sp);     // s - 2*r2*z   (2 n's at once)
            t = fma2(rp1, u1[k], t);          //   - 2*r1*y
            t = fma2(rp0, u0[k], t);          //   - 2*r0*x
            float fa, fb; upk2(t, fa, fb);
            mna[k] = fminf(mna[k], fa);
            mnb[k] = fminf(mnb[k], fb);
        }
    }

#pragma unroll
    for (int k = 0; k < MB; k++) {
        float v = fminf(mna[k], mnb[k]);
        // min over floats == max over reversed keys; identity 0 == untouched slot
        atomicMax(&g_min[b * NPTS + mbase + k * TPB + tid], fencMax(v));
    }

    // ---- last-block-done: final global reduction in whichever block finishes last ----
    __threadfence();
    if (tid == 0) {
        unsigned prev = atomicAdd(&g_count, 1u);
        isLast = (prev == NBLK - 1);
    }
    __syncthreads();
    if (!isLast) return;

    __threadfence();  // make all blocks' atomicMax / g_ssum stores visible

    // 256 threads, each reads 32 uint4 (fixed order -> deterministic),
    // re-arms the table to the all-zero identity for the next replay.
    float acc = 0.f;
    uint4* gm = (uint4*)g_min;
#pragma unroll 4
    for (int k = 0; k < (NB * NPTS) / (4 * TPB); k++) {
        int idx = tid + k * TPB;
        uint4 v = gm[idx];
        acc += fdecMax(v.x) + fdecMax(v.y);
        acc += fdecMax(v.z) + fdecMax(v.w);
        gm[idx] = make_uint4(0u, 0u, 0u, 0u);
    }
    if (tid < NSUM) acc += g_ssum[tid];

#pragma unroll
    for (int o = 16; o > 0; o >>= 1) acc += __shfl_down_sync(0xFFFFFFFFu, acc, o);
    if ((tid & 31) == 0) red[tid >> 5] = acc;
    __syncthreads();
    if (tid < (TPB / 32)) {
        acc = red[tid];
#pragma unroll
        for (int o = (TPB / 64); o > 0; o >>= 1) acc += __shfl_down_sync(0xFFu, acc, o);
        if (tid == 0) {
            float pt = acc * (1.f / ((float)NB * (float)NPTS));
            if (isnan(pt)) pt = 0.f;
            out[1] = pt;
            g_count = 0;   // re-arm counter for next graph replay
        }
    }
}

extern "C" void kernel_launch(void* const* d_in, const int* in_sizes, int n_in,
                              void* d_out, int out_size) {
    const float* pq  = (const float*)d_in[0];  // predquat (16,4)
    const float* gq  = (const float*)d_in[1];  // gtquat   (16,4)
    const float* pts = (const float*)d_in[2];  // points   (16,3,2048)
    float* out = (float*)d_out;                // [cos_loss, pt_loss]

    fused_kernel<<<NBLK, TPB>>>(pq, gq, pts, out);
}

// round 11
// speedup vs baseline: 1.1374x; 1.1374x over previous
#include <cuda_runtime.h>
#include <math.h>

#define NPTS   2048
#define NB     16
#define NCHUNK 8          // n-dimension split per batch
#define MSPLIT 2          // m-dimension split (2 blocks/SM)
#define TPB    256
#define MB     4          // m-points per thread (TPB*MB*MSPLIT = NPTS)
#define NBLK   (NB * NCHUNK * MSPLIT)   // 256
#define NSUM   (NB * NCHUNK)            // 128 s-sum slots (ms==0 blocks only)

typedef unsigned long long ull;

// Zero-initialized at module load. Key encoding makes 0 the identity of
// atomicMax (== +inf under min-over-floats), so no init pass is needed;
// the last block re-arms entries back to 0 each replay.
__device__ unsigned g_min[NB * NPTS];   // per-(b,m) running min, order-REVERSED keys
__device__ float    g_ssum[NSUM];       // per-(b,nc) partial sums of |p|^2
__device__ unsigned g_count = 0;        // arrival counter for last-block-done

// ---- packed f32x2 helpers (sm_103a) ----
__device__ __forceinline__ ull pk2(float a, float b) {
    ull r; asm("mov.b64 %0, {%1, %2};" : "=l"(r) : "f"(a), "f"(b)); return r;
}
__device__ __forceinline__ ull fma2(ull a, ull b, ull c) {
    ull d; asm("fma.rn.f32x2 %0, %1, %2, %3;" : "=l"(d) : "l"(a), "l"(b), "l"(c)); return d;
}
__device__ __forceinline__ void upk2(ull v, float& a, float& b) {
    asm("mov.b64 {%0, %1}, %2;" : "=f"(a), "=f"(b) : "l"(v));
}

// ---- order-REVERSING float<->uint keys: min(float) == max(key), identity = 0 ----
__device__ __forceinline__ unsigned fencMax(float f) {
    unsigned u = __float_as_uint(f);
    return (u & 0x80000000u) ? u : (~u & 0x7FFFFFFFu);
}
__device__ __forceinline__ float fdecMax(unsigned k) {
    unsigned u = (k & 0x80000000u) ? k : (~k & 0x7FFFFFFFu);
    return __uint_as_float(u);
}

__device__ __forceinline__ void quat2mat(const float q[4], float R[3][3]) {
    float w = q[0], x = q[1], y = q[2], z = q[3];
    R[0][0] = 1.f - 2.f * (y * y + z * z);
    R[0][1] = 2.f * (x * y - w * z);
    R[0][2] = 2.f * (x * z + w * y);
    R[1][0] = 2.f * (x * y + w * z);
    R[1][1] = 1.f - 2.f * (x * x + z * z);
    R[1][2] = 2.f * (y * z - w * x);
    R[2][0] = 2.f * (x * z - w * y);
    R[2][1] = 2.f * (y * z + w * x);
    R[2][2] = 1.f - 2.f * (x * x + y * y);
}

// Single fused kernel. grid = 16 batches x 8 n-chunks x 2 m-halves, 256 threads.
__global__ __launch_bounds__(TPB) void fused_kernel(const float* __restrict__ pq,
                                                    const float* __restrict__ gq,
                                                    const float* __restrict__ points,
                                                    float* __restrict__ out) {
    // n-table, packed-pair layout; +2 ull pad so the software-pipeline
    // prefetch of entry j+1 at j = TPB/2-1 stays in-bounds (values unused).
    __shared__ ull   smA[TPB + 2];      // [j*2+0]=r0 pair, [j*2+1]=r1 pair
    __shared__ ull   smB[TPB + 2];      // [j*2+0]=r2 pair, [j*2+1]=s  pair
    __shared__ float sA[9];
    __shared__ float red[TPB / 32];
    __shared__ bool  isLast;

    const int b   = blockIdx.x >> 4;                  // batch
    const int nc  = (blockIdx.x >> 1) & (NCHUNK - 1); // n-chunk
    const int ms  = blockIdx.x & (MSPLIT - 1);        // m-half
    const int tid = threadIdx.x;
    const float* __restrict__ P = points + b * 3 * NPTS;

    // ---- per-block quaternion math: A = Rp^T * Rg for this batch ----
    if (tid == 0) {
        float p[4], g[4];
#pragma unroll
        for (int i = 0; i < 4; i++) { p[i] = pq[b * 4 + i]; g[i] = gq[b * 4 + i]; }
        float np2 = 0.f, ng2 = 0.f;
#pragma unroll
        for (int i = 0; i < 4; i++) { np2 += p[i] * p[i]; ng2 += g[i] * g[i]; }
        float ip = 1.f / fmaxf(sqrtf(np2), 1e-8f);
        float ig = 1.f / fmaxf(sqrtf(ng2), 1e-8f);
#pragma unroll
        for (int i = 0; i < 4; i++) { p[i] *= ip; g[i] *= ig; }
        float Rp[3][3], Rg[3][3];
        quat2mat(p, Rp);
        quat2mat(g, Rg);
#pragma unroll
        for (int i = 0; i < 3; i++)
#pragma unroll
            for (int j = 0; j < 3; j++) {
                float a = 0.f;
#pragma unroll
                for (int k = 0; k < 3; k++) a += Rp[k][i] * Rg[k][j];
                sA[i * 3 + j] = a;
            }
    }

    // ---- cos_loss: block 0, warp 0 (lanes 0..15 own one batch each) ----
    if (blockIdx.x == 0 && tid < 32) {
        float cos_term = 0.f;
        if (tid < NB) {
            float p[4], g[4];
#pragma unroll
            for (int i = 0; i < 4; i++) { p[i] = pq[tid * 4 + i]; g[i] = gq[tid * 4 + i]; }
            float dot = 0.f, np2 = 0.f, ng2 = 0.f;
#pragma unroll
            for (int i = 0; i < 4; i++) {
                dot += p[i] * g[i]; np2 += p[i] * p[i]; ng2 += g[i] * g[i];
            }
            cos_term = 1.f - dot / fmaxf(sqrtf(np2) * sqrtf(ng2), 1e-8f);
        }
#pragma unroll
        for (int o = 16; o > 0; o >>= 1) cos_term += __shfl_down_sync(0xFFFFFFFFu, cos_term, o);
        if (tid == 0) out[0] = cos_term * (1.f / (float)NB);
    }
    __syncthreads();

    const float A00 = sA[0], A01 = sA[1], A02 = sA[2];
    const float A10 = sA[3], A11 = sA[4], A12 = sA[5];
    const float A20 = sA[6], A21 = sA[7], A22 = sA[8];

    // ---- Phase 1: r/s table for this block's 256 n-points (+ s-sum, ms==0 only) ----
    {
        int n = nc * TPB + tid;
        float x = P[n], y = P[NPTS + n], z = P[2 * NPTS + n];
        float r0 = A00 * x + A01 * y + A02 * z;
        float r1 = A10 * x + A11 * y + A12 * z;
        float r2 = A20 * x + A21 * y + A22 * z;
        float s  = x * x + y * y + z * z;
        float* fA = (float*)smA;
        float* fB = (float*)smB;
        int j = tid >> 1, h = tid & 1;
        fA[j * 4 + h]     = r0;
        fA[j * 4 + 2 + h] = r1;
        fB[j * 4 + h]     = r2;
        fB[j * 4 + 2 + h] = s;

        if (ms == 0) {
            float t = s;
#pragma unroll
            for (int o = 16; o > 0; o >>= 1) t += __shfl_down_sync(0xFFFFFFFFu, t, o);
            if ((tid & 31) == 0) red[tid >> 5] = t;
        }
    }
    __syncthreads();
    if (ms == 0 && tid < (TPB / 32)) {
        float t = red[tid];
#pragma unroll
        for (int o = (TPB / 64); o > 0; o >>= 1) t += __shfl_down_sync(0xFFu, t, o);
        if (tid == 0) g_ssum[b * NCHUNK + nc] = t;
    }

    // ---- Phase 2: each thread owns m = ms*1024 + k*256 + tid, k in [0,4) ----
    const int mbase = ms * (NPTS / MSPLIT);
    ull u0[MB], u1[MB], u2[MB];
#pragma unroll
    for (int k = 0; k < MB; k++) {
        int m = mbase + k * TPB + tid;
        float mx = -2.f * P[m];
        float my = -2.f * P[NPTS + m];
        float mz = -2.f * P[2 * NPTS + m];
        u0[k] = pk2(mx, mx);
        u1[k] = pk2(my, my);
        u2[k] = pk2(mz, mz);
    }

    float mna[MB], mnb[MB];
#pragma unroll
    for (int k = 0; k < MB; k++) { mna[k] = INFINITY; mnb[k] = INFINITY; }

    const ull* __restrict__ pA = smA;
    const ull* __restrict__ pB = smB;

    // Software-pipelined scan: prefetch n-pair j+1 while computing j, so the
    // 29-cyc LDS latency is hidden behind ~25 independent math instructions.
    ull c0 = pA[0], c1 = pA[1], c2 = pB[0], c3 = pB[1];
#pragma unroll 4
    for (int j = 0; j < TPB / 2; j++) {
        ull n0 = pA[j * 2 + 2];
        ull n1 = pA[j * 2 + 3];
        ull n2 = pB[j * 2 + 2];
        ull n3 = pB[j * 2 + 3];
#pragma unroll
        for (int k = 0; k < MB; k++) {
            ull t = fma2(c2, u2[k], c3);      // s - 2*r2*z   (2 n's at once)
            t = fma2(c1, u1[k], t);           //   - 2*r1*y
            t = fma2(c0, u0[k], t);           //   - 2*r0*x
            float fa, fb; upk2(t, fa, fb);
            mna[k] = fminf(mna[k], fa);
            mnb[k] = fminf(mnb[k], fb);
        }
        c0 = n0; c1 = n1; c2 = n2; c3 = n3;
    }

#pragma unroll
    for (int k = 0; k < MB; k++) {
        float v = fminf(mna[k], mnb[k]);
        // min over floats == max over reversed keys; identity 0 == untouched slot
        atomicMax(&g_min[b * NPTS + mbase + k * TPB + tid], fencMax(v));
    }

    // ---- last-block-done: final global reduction in whichever block finishes last ----
    __threadfence();
    if (tid == 0) {
        unsigned prev = atomicAdd(&g_count, 1u);
        isLast = (prev == NBLK - 1);
    }
    __syncthreads();
    if (!isLast) return;

    __threadfence();  // make all blocks' atomicMax / g_ssum stores visible

    // 256 threads, each reads 32 uint4 (fixed order -> deterministic),
    // re-arms the table to the all-zero identity for the next replay.
    float acc = 0.f;
    uint4* gm = (uint4*)g_min;
#pragma unroll 4
    for (int k = 0; k < (NB * NPTS) / (4 * TPB); k++) {
        int idx = tid + k * TPB;
        uint4 v = gm[idx];
        acc += fdecMax(v.x) + fdecMax(v.y);
        acc += fdecMax(v.z) + fdecMax(v.w);
        gm[idx] = make_uint4(0u, 0u, 0u, 0u);
    }
    if (tid < NSUM) acc += g_ssum[tid];

#pragma unroll
    for (int o = 16; o > 0; o >>= 1) acc += __shfl_down_sync(0xFFFFFFFFu, acc, o);
    if ((tid & 31) == 0) red[tid >> 5] = acc;
    __syncthreads();
    if (tid < (TPB / 32)) {
        acc = red[tid];
#pragma unroll
        for (int o = (TPB / 64); o > 0; o >>= 1) acc += __shfl_down_sync(0xFFu, acc, o);
        if (tid == 0) {
            float pt = acc * (1.f / ((float)NB * (float)NPTS));
            if (isnan(pt)) pt = 0.f;
            out[1] = pt;
            g_count = 0;   // re-arm counter for next graph replay
        }
    }
}

extern "C" void kernel_launch(void* const* d_in, const int* in_sizes, int n_in,
                              void* d_out, int out_size) {
    const float* pq  = (const float*)d_in[0];  // predquat (16,4)
    const float* gq  = (const float*)d_in[1];  // gtquat   (16,4)
    const float* pts = (const float*)d_in[2];  // points   (16,3,2048)
    float* out = (float*)d_out;                // [cos_loss, pt_loss]

    fused_kernel<<<NBLK, TPB>>>(pq, gq, pts, out);
}

// round 12
// speedup vs baseline: 1.2470x; 1.0964x over previous
#include <cuda_runtime.h>
#include <math.h>

#define NPTS   2048
#define NB     16
#define NCHUNK 8          // n-dimension split per batch
#define TPB    512
#define MB     4          // m-points per thread (TPB*MB = NPTS)
#define NBLK   (NB * NCHUNK)            // 128 blocks -> one wave on 148 SMs
#define NSUM   (NB * NCHUNK)            // 128 s-sum slots

// Zero-initialized at module load. Key encoding makes 0 the identity of
// atomicMax (== +inf under min-over-floats), so no init pass is needed;
// the last block re-arms entries back to 0 each replay.
__device__ unsigned g_min[NB * NPTS];   // per-(b,m) running min, order-REVERSED keys
__device__ float    g_ssum[NSUM];       // per-(b,nc) partial sums of |p|^2
__device__ unsigned g_count = 0;        // arrival counter for last-block-done

// ---- order-REVERSING float<->uint keys: min(float) == max(key), identity = 0 ----
__device__ __forceinline__ unsigned fencMax(float f) {
    unsigned u = __float_as_uint(f);
    return (u & 0x80000000u) ? u : (~u & 0x7FFFFFFFu);
}
__device__ __forceinline__ float fdecMax(unsigned k) {
    unsigned u = (k & 0x80000000u) ? k : (~k & 0x7FFFFFFFu);
    return __uint_as_float(u);
}

__device__ __forceinline__ void quat2mat(const float q[4], float R[3][3]) {
    float w = q[0], x = q[1], y = q[2], z = q[3];
    R[0][0] = 1.f - 2.f * (y * y + z * z);
    R[0][1] = 2.f * (x * y - w * z);
    R[0][2] = 2.f * (x * z + w * y);
    R[1][0] = 2.f * (x * y + w * z);
    R[1][1] = 1.f - 2.f * (x * x + z * z);
    R[1][2] = 2.f * (y * z - w * x);
    R[2][0] = 2.f * (x * z - w * y);
    R[2][1] = 2.f * (y * z + w * x);
    R[2][2] = 1.f - 2.f * (x * x + y * y);
}

// Single fused kernel. grid = 16 batches x 8 n-chunks, 512 threads (one wave).
__global__ __launch_bounds__(TPB, 1) void fused_kernel(const float* __restrict__ pq,
                                                       const float* __restrict__ gq,
                                                       const float* __restrict__ points,
                                                       float* __restrict__ out) {
    // n-table: one float4 per n-point: (r0, r1, r2, s)
    __shared__ float4 smN[NCHUNK == 8 ? (NPTS / NCHUNK) : 256];   // 256 entries
    __shared__ float  sA[9];
    __shared__ float  red[TPB / 32];
    __shared__ bool   isLast;

    const int b   = blockIdx.x >> 3;                  // batch
    const int nc  = blockIdx.x & (NCHUNK - 1);        // n-chunk
    const int tid = threadIdx.x;
    const float* __restrict__ P = points + b * 3 * NPTS;

    // ---- per-block quaternion math: A = Rp^T * Rg for this batch ----
    if (tid == 0) {
        float p[4], g[4];
#pragma unroll
        for (int i = 0; i < 4; i++) { p[i] = pq[b * 4 + i]; g[i] = gq[b * 4 + i]; }
        float np2 = 0.f, ng2 = 0.f;
#pragma unroll
        for (int i = 0; i < 4; i++) { np2 += p[i] * p[i]; ng2 += g[i] * g[i]; }
        float ip = 1.f / fmaxf(sqrtf(np2), 1e-8f);
        float ig = 1.f / fmaxf(sqrtf(ng2), 1e-8f);
#pragma unroll
        for (int i = 0; i < 4; i++) { p[i] *= ip; g[i] *= ig; }
        float Rp[3][3], Rg[3][3];
        quat2mat(p, Rp);
        quat2mat(g, Rg);
#pragma unroll
        for (int i = 0; i < 3; i++)
#pragma unroll
            for (int j = 0; j < 3; j++) {
                float a = 0.f;
#pragma unroll
                for (int k = 0; k < 3; k++) a += Rp[k][i] * Rg[k][j];
                sA[i * 3 + j] = a;
            }
    }

    // ---- cos_loss: block 0, warp 0 (lanes 0..15 own one batch each) ----
    if (blockIdx.x == 0 && tid < 32) {
        float cos_term = 0.f;
        if (tid < NB) {
            float p[4], g[4];
#pragma unroll
            for (int i = 0; i < 4; i++) { p[i] = pq[tid * 4 + i]; g[i] = gq[tid * 4 + i]; }
            float dot = 0.f, np2 = 0.f, ng2 = 0.f;
#pragma unroll
            for (int i = 0; i < 4; i++) {
                dot += p[i] * g[i]; np2 += p[i] * p[i]; ng2 += g[i] * g[i];
            }
            cos_term = 1.f - dot / fmaxf(sqrtf(np2) * sqrtf(ng2), 1e-8f);
        }
#pragma unroll
        for (int o = 16; o > 0; o >>= 1) cos_term += __shfl_down_sync(0xFFFFFFFFu, cos_term, o);
        if (tid == 0) out[0] = cos_term * (1.f / (float)NB);
    }
    __syncthreads();

    const float A00 = sA[0], A01 = sA[1], A02 = sA[2];
    const float A10 = sA[3], A11 = sA[4], A12 = sA[5];
    const float A20 = sA[6], A21 = sA[7], A22 = sA[8];

    // ---- Phase 1: r/s table for this block's 256 n-points + s-sum ----
    const int NLOC = NPTS / NCHUNK;   // 256
    if (tid < NLOC) {
        int n = nc * NLOC + tid;
        float x = P[n], y = P[NPTS + n], z = P[2 * NPTS + n];
        float r0 = fmaf(A00, x, fmaf(A01, y, A02 * z));
        float r1 = fmaf(A10, x, fmaf(A11, y, A12 * z));
        float r2 = fmaf(A20, x, fmaf(A21, y, A22 * z));
        float s  = fmaf(x, x, fmaf(y, y, z * z));
        smN[tid] = make_float4(r0, r1, r2, s);

        // warp-reduce s across the 8 building warps
        float t = s;
#pragma unroll
        for (int o = 16; o > 0; o >>= 1) t += __shfl_down_sync(0xFFFFFFFFu, t, o);
        if ((tid & 31) == 0) red[tid >> 5] = t;
    }
    __syncthreads();
    if (tid == 0) {
        float t = 0.f;
#pragma unroll
        for (int w = 0; w < NLOC / 32; w++) t += red[w];
        g_ssum[blockIdx.x] = t;
    }

    // ---- Phase 2: each thread owns m = k*512 + tid, k in [0,4) ----
    float u0[MB], u1[MB], u2[MB];
#pragma unroll
    for (int k = 0; k < MB; k++) {
        int m = k * TPB + tid;
        u0[k] = -2.f * P[m];
        u1[k] = -2.f * P[NPTS + m];
        u2[k] = -2.f * P[2 * NPTS + m];
    }

    float mn[MB];
#pragma unroll
    for (int k = 0; k < MB; k++) mn[k] = INFINITY;

#pragma unroll 4
    for (int j = 0; j < NLOC; j++) {
        float4 t = smN[j];   // broadcast LDS.128: (r0, r1, r2, s)
#pragma unroll
        for (int k = 0; k < MB; k++) {
            float v = fmaf(u2[k], t.z, t.w);   // s - 2*r2*z
            v = fmaf(u1[k], t.y, v);           //   - 2*r1*y
            v = fmaf(u0[k], t.x, v);           //   - 2*r0*x
            mn[k] = fminf(mn[k], v);
        }
    }

#pragma unroll
    for (int k = 0; k < MB; k++) {
        // min over floats == max over reversed keys; identity 0 == untouched slot
        atomicMax(&g_min[b * NPTS + k * TPB + tid], fencMax(mn[k]));
    }

    // ---- last-block-done: final global reduction in whichever block finishes last ----
    __threadfence();
    if (tid == 0) {
        unsigned prev = atomicAdd(&g_count, 1u);
        isLast = (prev == NBLK - 1);
    }
    __syncthreads();
    if (!isLast) return;

    __threadfence();  // make all blocks' atomicMax / g_ssum stores visible

    // 512 threads, each reads 16 uint4 (fixed order -> deterministic),
    // re-arms the table to the all-zero identity for the next replay.
    float acc = 0.f;
    uint4* gm = (uint4*)g_min;
#pragma unroll 4
    for (int k = 0; k < (NB * NPTS) / (4 * TPB); k++) {
        int idx = tid + k * TPB;
        uint4 v = gm[idx];
        acc += fdecMax(v.x) + fdecMax(v.y);
        acc += fdecMax(v.z) + fdecMax(v.w);
        gm[idx] = make_uint4(0u, 0u, 0u, 0u);
    }
    if (tid < NSUM) acc += g_ssum[tid];

#pragma unroll
    for (int o = 16; o > 0; o >>= 1) acc += __shfl_down_sync(0xFFFFFFFFu, acc, o);
    if ((tid & 31) == 0) red[tid >> 5] = acc;
    __syncthreads();
    if (tid < 32) {
        acc = (tid < (TPB / 32)) ? red[tid] : 0.f;
#pragma unroll
        for (int o = 16; o > 0; o >>= 1) acc += __shfl_down_sync(0xFFFFFFFFu, acc, o);
        if (tid == 0) {
            float pt = acc * (1.f / ((float)NB * (float)NPTS));
            if (isnan(pt)) pt = 0.f;
            out[1] = pt;
            g_count = 0;   // re-arm counter for next graph replay
        }
    }
}

extern "C" void kernel_launch(void* const* d_in, const int* in_sizes, int n_in,
                              void* d_out, int out_size) {
    const float* pq  = (const float*)d_in[0];  // predquat (16,4)
    const float* gq  = (const float*)d_in[1];  // gtquat   (16,4)
    const float* pts = (const float*)d_in[2];  // points   (16,3,2048)
    float* out = (float*)d_out;                // [cos_loss, pt_loss]

    fused_kernel<<<NBLK, TPB>>>(pq, gq, pts, out);
}